// round 6
// baseline (speedup 1.0000x reference)
#include <cuda_runtime.h>
#include <math.h>

#define NB 64      // batch
#define NT 1024    // seq len
#define ND 256     // input dim
#define NH 1024    // hidden
#define NC 1000    // classes
#define RCTAS 128  // persistent recurrence CTAs (1 CTA/SM resident)

typedef unsigned long long u64;

// ---------------- scratch (device globals) ----------------
// g_xprojT[t] starts as xproj_t (xproj_kernel); recurrence red-accumulates
// W_hh*h_{t-1} into slice t. h_t = modrelu(z_t) computed on the fly by readers.
__device__ float g_xprojT[NT * NH * NB];   // [t][n][b]  256 MB
__device__ unsigned g_arr[16];             // per n-column-group arrival counters

// ---------------- sync / math primitives ----------------
__device__ __forceinline__ unsigned ld_acq(const unsigned* p) {
    unsigned v;
    asm volatile("ld.global.acquire.gpu.u32 %0, [%1];" : "=r"(v) : "l"(p));
    return v;
}
#define FMA2(d, a, b) asm("fma.rn.f32x2 %0, %1, %2, %0;" : "+l"(d) : "l"(a), "l"(b))
__device__ __forceinline__ float lo32(u64 v) { return __uint_as_float((unsigned)v); }
__device__ __forceinline__ float hi32(u64 v) { return __uint_as_float((unsigned)(v >> 32)); }

__device__ __forceinline__ void red_add_v4(float* p, float v0, float v1, float v2, float v3) {
    asm volatile("red.global.add.v4.f32 [%0], {%1, %2, %3, %4};"
                 :: "l"(p), "f"(v0), "f"(v1), "f"(v2), "f"(v3) : "memory");
}
__device__ __forceinline__ float modrelu(float z, float bm) {
    float a = fabsf(z) + bm;
    return (a > 0.0f) ? copysignf(a, z) : 0.0f;
}

// ---------------- init: reset dataflow counters each launch ----------------
__global__ void init_kernel() {
    if (threadIdx.x < 16) g_arr[threadIdx.x] = 0u;
}

// Thread map shared by both FFMA2 GEMMs (256 threads, 64b x 64n tile,
// thread microtile = 4 batches (2 f32x2 pairs) x 4 n-cols):
//   tx = tid & 7, ty = (tid >> 3) & 15, tz = tid >> 7
//   n-quad g = tz*8 + tx (16 quads), ncol = g*4, b = ty*4
// A (As[k][64b]) loaded as natural batch pairs; B duplicated (w,w) in two
// banks Bsd1/Bsd2 [k][64]: Bsd1[k][g*4..] = dup(w[n], w[n+1]),
// Bsd2[k][g*4..] = dup(w[n+2], w[n+3]).

// inner step: 3 LDS.128 + 8 FFMA2
#define GEMM_KK(As_, B1_, B2_, kk_, LDA_)                                     \
    {                                                                          \
        ulonglong2 a   = *(const ulonglong2*)((As_) + (kk_) * (LDA_) + ty * 4);\
        ulonglong2 b01 = *(const ulonglong2*)((B1_) + (kk_) * 64 + g4);        \
        ulonglong2 b23 = *(const ulonglong2*)((B2_) + (kk_) * 64 + g4);        \
        FMA2(acc[0][0], a.x, b01.x); FMA2(acc[0][1], a.x, b01.y);              \
        FMA2(acc[0][2], a.x, b23.x); FMA2(acc[0][3], a.x, b23.y);              \
        FMA2(acc[1][0], a.y, b01.x); FMA2(acc[1][1], a.y, b01.y);              \
        FMA2(acc[1][2], a.y, b23.x); FMA2(acc[1][3], a.y, b23.y);              \
    }

// ---------------- kernel 1: xprojT[t][n][b] = x[b][t][:] . w_ih[n][:] (FFMA2) ----------------
__global__ __launch_bounds__(256) void xproj_kernel(
    const float* __restrict__ x, const float* __restrict__ w_ih)
{
    __shared__ float As[32 * 64];     // [k][b]   8 KB
    __shared__ float Bsd1[32 * 64];   // dup cols {0,1} of each quad, 8 KB
    __shared__ float Bsd2[32 * 64];   // dup cols {2,3}, 8 KB

    const int t0 = blockIdx.x;
    const int n0 = blockIdx.y * 64;
    const int tid = threadIdx.x;
    const int tx = tid & 7, ty = (tid >> 3) & 15, tz = tid >> 7;
    const int g4 = (tz * 8 + tx) * 4;

    u64 acc[2][4];
    #pragma unroll
    for (int i = 0; i < 2; i++)
        #pragma unroll
        for (int j = 0; j < 4; j++) acc[i][j] = 0ull;

    for (int c = 0; c < 8; c++) {
        const int kbase = c * 32;
        __syncthreads();
        // stage A: As[k][b] = x[b][t0][kbase+k]
        #pragma unroll
        for (int it = 0; it < 2; it++) {
            int f4 = it * 256 + tid;            // 512 float4 = 64b x 32k
            int b = f4 & 63, kq = (f4 >> 6) * 4;
            float4 xa = __ldg((const float4*)(x + (long)b * (NT * ND) +
                                              (long)t0 * ND + kbase + kq));
            As[(kq + 0) * 64 + b] = xa.x;
            As[(kq + 1) * 64 + b] = xa.y;
            As[(kq + 2) * 64 + b] = xa.z;
            As[(kq + 3) * 64 + b] = xa.w;
        }
        // stage B dup
        #pragma unroll
        for (int it = 0; it < 2; it++) {
            int f4 = it * 256 + tid;
            int np = f4 & 63, kq = (f4 >> 6) * 4;
            int gq = np >> 2, r = np & 3;
            float* dst = (r < 2 ? Bsd1 : Bsd2) + gq * 4 + 2 * (r & 1);
            float4 w = __ldg((const float4*)(w_ih + (long)(n0 + np) * ND + kbase + kq));
            *(float2*)(dst + (kq + 0) * 64) = make_float2(w.x, w.x);
            *(float2*)(dst + (kq + 1) * 64) = make_float2(w.y, w.y);
            *(float2*)(dst + (kq + 2) * 64) = make_float2(w.z, w.z);
            *(float2*)(dst + (kq + 3) * 64) = make_float2(w.w, w.w);
        }
        __syncthreads();
        #pragma unroll
        for (int kk = 0; kk < 32; kk++) GEMM_KK(As, Bsd1, Bsd2, kk, 64)
    }

    // store: g_xprojT[t0][n0 + g4 + j][ty*4 .. +3]
    float* zdst = g_xprojT + ((long)t0 * NH + n0 + g4) * NB + ty * 4;
    #pragma unroll
    for (int j = 0; j < 4; j++) {
        float4 v = make_float4(lo32(acc[0][j]), hi32(acc[0][j]),
                               lo32(acc[1][j]), hi32(acc[1][j]));
        *(float4*)(zdst + (long)j * NB) = v;
    }
}

// ---------------- kernel 2: persistent recurrence (dataflow sync) ----------------
// CTA (nc = cta&15, kc = cta>>4). Persistent dup W in smem (one-time).
// Step t: wait groups {2kc,2kc+1} at 8(t-1) -> stage h=modrelu(z_{t-1}) chunk kc
// (straight copy) -> FFMA2 GEMM -> red.v4 into z_t -> fence -> arrive arr[nc].
__global__ __launch_bounds__(256) void recur_kernel(
    const float* __restrict__ w_hh, const float* __restrict__ b_mod)
{
    extern __shared__ float sm[];
    float* As   = sm;                  // [128][64]  32 KB (h staged per step)
    float* Bsd1 = sm + 128 * 64;       // [128][64]  32 KB (dup W, one-time)
    float* Bsd2 = sm + 2 * 128 * 64;   // [128][64]  32 KB

    const int tid = threadIdx.x;
    const int cta = blockIdx.x;
    const int nc = cta & 15;
    const int kc = cta >> 4;
    const int tx = tid & 7, ty = (tid >> 3) & 15, tz = tid >> 7;
    const int g4 = (tz * 8 + tx) * 4;

    // ---- one-time: W_hh slice, duplicated, into persistent smem ----
    #pragma unroll
    for (int it = 0; it < 8; it++) {
        int f4 = it * 256 + tid;                 // 2048 float4 = 64n x 128k
        int np = f4 >> 5, k0 = (f4 & 31) * 4;
        int gq = np >> 2, r = np & 3;
        float* dst = (r < 2 ? Bsd1 : Bsd2) + gq * 4 + 2 * (r & 1);
        float4 w = __ldg((const float4*)(w_hh + (long)(nc * 64 + np) * NH + kc * 128 + k0));
        *(float2*)(dst + (k0 + 0) * 64) = make_float2(w.x, w.x);
        *(float2*)(dst + (k0 + 1) * 64) = make_float2(w.y, w.y);
        *(float2*)(dst + (k0 + 2) * 64) = make_float2(w.z, w.z);
        *(float2*)(dst + (k0 + 3) * 64) = make_float2(w.w, w.w);
    }

    for (int t = 1; t < NT; t++) {
        // ---- wait: the two column groups covering chunk kc of z_{t-1} ----
        if (t > 1) {
            unsigned target = (unsigned)(8 * (t - 1));
            if (tid == 0)  while (ld_acq(&g_arr[2 * kc]) < target) {}
            if (tid == 32) while (ld_acq(&g_arr[2 * kc + 1]) < target) {}
        }
        __syncthreads();

        // ---- stage: As[k][b] = modrelu(z_{t-1}[kc*128+k][b]) — straight copy ----
        {
            const float4* zsrc = (const float4*)(g_xprojT +
                                 ((long)(t - 1) * NH + kc * 128) * NB);
            #pragma unroll
            for (int it = 0; it < 8; it++) {
                int f4 = it * 256 + tid;            // 2048 float4 = 128k x 64b
                int k = f4 >> 4;
                float4 z = __ldcg(zsrc + f4);
                float bm = __ldg(&b_mod[kc * 128 + k]);
                float4 h;
                h.x = modrelu(z.x, bm); h.y = modrelu(z.y, bm);
                h.z = modrelu(z.z, bm); h.w = modrelu(z.w, bm);
                *((float4*)As + f4) = h;
            }
        }
        __syncthreads();

        // ---- GEMM: 128 kk x (3 LDS.128 + 8 FFMA2) ----
        u64 acc[2][4];
        #pragma unroll
        for (int i = 0; i < 2; i++)
            #pragma unroll
            for (int j = 0; j < 4; j++) acc[i][j] = 0ull;

        #pragma unroll 8
        for (int kk = 0; kk < 128; kk++) GEMM_KK(As, Bsd1, Bsd2, kk, 64)

        // ---- red-accumulate partials into z_t ----
        {
            float* zdst = g_xprojT + ((long)t * NH + nc * 64 + g4) * NB + ty * 4;
            #pragma unroll
            for (int j = 0; j < 4; j++)
                red_add_v4(zdst + (long)j * NB,
                           lo32(acc[0][j]), hi32(acc[0][j]),
                           lo32(acc[1][j]), hi32(acc[1][j]));
        }

        // ---- arrive ----
        __syncthreads();
        if (tid == 0) {
            __threadfence();
            atomicAdd(&g_arr[nc], 1u);
        }
    }
}

// ---------------- kernel 3: fc head out[b][c] = modrelu(z_last)[:,b] . w_fc[c][:] + b_fc[c]
__global__ __launch_bounds__(256) void fc_kernel(
    const float* __restrict__ w_fc, const float* __restrict__ b_fc,
    const float* __restrict__ b_mod, float* __restrict__ out)
{
    __shared__ float As[64][64];   // [k][b] = h_last slab
    __shared__ float Bs[64][64];   // [k][c']
    const int n0 = blockIdx.x * 64;
    const int tid = threadIdx.x;
    const int tx = tid & 15, ty = tid >> 4;
    const float* zlast = g_xprojT + (long)(NT - 1) * NH * NB;
    float acc[4][4] = {};

    for (int s = 0; s < 16; s++) {
        __syncthreads();
        #pragma unroll
        for (int it = 0; it < 4; it++) {
            int f4 = it * 256 + tid;
            int n = s * 64 + (f4 >> 4);
            float4 z = __ldcg((const float4*)zlast + s * 1024 + f4);
            float bm = __ldg(&b_mod[n]);
            float4 h;
            h.x = modrelu(z.x, bm); h.y = modrelu(z.y, bm);
            h.z = modrelu(z.z, bm); h.w = modrelu(z.w, bm);
            ((float4*)As)[f4] = h;
        }
        #pragma unroll
        for (int it = 0; it < 4; it++) {
            int f4 = it * 256 + tid;
            int np = f4 >> 4, k0 = (f4 & 15) * 4;
            int row = n0 + np; if (row >= NC) row = NC - 1;
            float4 w = *(const float4*)(w_fc + (long)row * NH + s * 64 + k0);
            Bs[k0 + 0][np] = w.x; Bs[k0 + 1][np] = w.y;
            Bs[k0 + 2][np] = w.z; Bs[k0 + 3][np] = w.w;
        }
        __syncthreads();
        #pragma unroll 8
        for (int kk = 0; kk < 64; kk++) {
            float4 av = *(const float4*)(&As[kk][ty * 4]);
            float4 bv = *(const float4*)(&Bs[kk][tx * 4]);
            float a[4] = {av.x, av.y, av.z, av.w};
            float b[4] = {bv.x, bv.y, bv.z, bv.w};
            #pragma unroll
            for (int i = 0; i < 4; i++)
                #pragma unroll
                for (int j = 0; j < 4; j++)
                    acc[i][j] += a[i] * b[j];
        }
    }
    #pragma unroll
    for (int i = 0; i < 4; i++) {
        #pragma unroll
        for (int j = 0; j < 4; j++) {
            int c = n0 + tx * 4 + j;
            if (c < NC) out[(long)(ty * 4 + i) * NC + c] = acc[i][j] + __ldg(&b_fc[c]);
        }
    }
}

// ---------------- launch ----------------
extern "C" void kernel_launch(void* const* d_in, const int* in_sizes, int n_in,
                              void* d_out, int out_size)
{
    const float* x     = (const float*)d_in[0];  // [64,1024,256]
    const float* w_ih  = (const float*)d_in[1];  // [1024,256]
    const float* w_hh  = (const float*)d_in[2];  // [1024,1024]
    const float* b_mod = (const float*)d_in[3];  // [1024]
    const float* w_fc  = (const float*)d_in[4];  // [1000,1024]
    const float* b_fc  = (const float*)d_in[5];  // [1000]
    float* out = (float*)d_out;                  // [64,1000]

    cudaFuncSetAttribute(recur_kernel, cudaFuncAttributeMaxDynamicSharedMemorySize, 98304);

    init_kernel<<<1, 32>>>();
    dim3 gx(NT, NH / 64);
    xproj_kernel<<<gx, 256>>>(x, w_ih);
    recur_kernel<<<RCTAS, 256, 98304>>>(w_hh, b_mod);
    fc_kernel<<<(NC + 63) / 64, 256>>>(w_fc, b_fc, b_mod, out);
}

// round 7
// speedup vs baseline: 1.1932x; 1.1932x over previous
#include <cuda_runtime.h>
#include <math.h>

#define NB 64      // batch
#define NT 1024    // seq len
#define ND 256     // input dim
#define NH 1024    // hidden
#define NC 1000    // classes
#define RCTAS 128  // persistent recurrence CTAs (1 CTA/SM resident)

typedef unsigned long long u64;

// ---------------- scratch (device globals) ----------------
// g_xprojT[t] starts as xproj_t (xproj kernel); recurrence red-accumulates
// W_hh*h_{t-1} into slice t. h_t = modrelu(z_t) computed on the fly by readers.
__device__ float g_xprojT[NT * NH * NB];   // [t][n][b]  256 MB
__device__ float g_xT[NT * ND * NB];       // [t][d][b]  67 MB (transposed x)
__device__ float g_wihT[ND * NH];          // [d][n]  1 MB (transposed w_ih)
__device__ unsigned g_arr[16];             // per n-column-group arrival counters

// ---------------- sync / math primitives ----------------
__device__ __forceinline__ unsigned ld_acq(const unsigned* p) {
    unsigned v;
    asm volatile("ld.global.acquire.gpu.u32 %0, [%1];" : "=r"(v) : "l"(p));
    return v;
}
#define FMA2(d, a, b) asm("fma.rn.f32x2 %0, %1, %2, %0;" : "+l"(d) : "l"(a), "l"(b))
__device__ __forceinline__ float lo32(u64 v) { return __uint_as_float((unsigned)v); }
__device__ __forceinline__ float hi32(u64 v) { return __uint_as_float((unsigned)(v >> 32)); }

__device__ __forceinline__ void red_add_v4(float* p, float v0, float v1, float v2, float v3) {
    asm volatile("red.global.add.v4.f32 [%0], {%1, %2, %3, %4};"
                 :: "l"(p), "f"(v0), "f"(v1), "f"(v2), "f"(v3) : "memory");
}
__device__ __forceinline__ float modrelu(float z, float bm) {
    float a = fabsf(z) + bm;
    return (a > 0.0f) ? copysignf(a, z) : 0.0f;
}

// ---------------- init: reset dataflow counters each launch ----------------
__global__ void init_kernel() {
    if (threadIdx.x < 16) g_arr[threadIdx.x] = 0u;
}

// ---------------- transpose kernels ----------------
// xT[t][d][b] = x[b][t][d].  grid (NT, ND/64), block 256.
__global__ __launch_bounds__(256) void xpose_kernel(const float* __restrict__ x) {
    __shared__ float T[64][65];
    const int t0 = blockIdx.x;
    const int d0 = blockIdx.y * 64;
    const int tid = threadIdx.x;
    const int b = tid & 63;
    #pragma unroll
    for (int it = 0; it < 4; it++) {
        int d4 = (tid >> 6) * 4 + it * 16;
        float4 v = __ldg((const float4*)(x + (long)b * (NT * ND) + (long)t0 * ND + d0 + d4));
        T[d4 + 0][b] = v.x; T[d4 + 1][b] = v.y;
        T[d4 + 2][b] = v.z; T[d4 + 3][b] = v.w;
    }
    __syncthreads();
    #pragma unroll
    for (int it = 0; it < 4; it++) {
        int dr = it * 16 + (tid >> 4);
        int b4 = (tid & 15) * 4;
        float4 v = make_float4(T[dr][b4], T[dr][b4 + 1], T[dr][b4 + 2], T[dr][b4 + 3]);
        *(float4*)(g_xT + ((long)t0 * ND + d0 + dr) * NB + b4) = v;
    }
}

// wihT[d][n] = w_ih[n][d].  grid (NH/64, ND/64), block 256.
__global__ __launch_bounds__(256) void wpose_kernel(const float* __restrict__ w_ih) {
    __shared__ float T[64][65];
    const int n0 = blockIdx.x * 64;
    const int d0 = blockIdx.y * 64;
    const int tid = threadIdx.x;
    const int n = tid & 63;
    #pragma unroll
    for (int it = 0; it < 4; it++) {
        int d4 = (tid >> 6) * 4 + it * 16;
        float4 v = __ldg((const float4*)(w_ih + (long)(n0 + n) * ND + d0 + d4));
        T[d4 + 0][n] = v.x; T[d4 + 1][n] = v.y;
        T[d4 + 2][n] = v.z; T[d4 + 3][n] = v.w;
    }
    __syncthreads();
    #pragma unroll
    for (int it = 0; it < 4; it++) {
        int dr = it * 16 + (tid >> 4);
        int n4 = (tid & 15) * 4;
        float4 v = make_float4(T[dr][n4], T[dr][n4 + 1], T[dr][n4 + 2], T[dr][n4 + 3]);
        *(float4*)(g_wihT + (long)(d0 + dr) * NH + n0 + n4) = v;
    }
}

// ---------------- kernel 1: xprojT[t][n][b] = sum_d xT[t][d][b] * wihT[d][n] ----------------
// FFMA2 clone of the recurrence microkernel: 4 passes of 64 k.
// Thread map (R5-proven): tx = tid&15, ty = tid>>4; microtile 4b x 4n.
__global__ __launch_bounds__(256) void xproj_kernel() {
    __shared__ float As_dup[64 * 128];   // [k][2b dup]  32 KB
    __shared__ float Bs[64 * 64];        // [k][n]       16 KB

    const int t0 = blockIdx.x;
    const int n0 = blockIdx.y * 64;
    const int tid = threadIdx.x;
    const int tx = tid & 15, ty = tid >> 4;

    u64 acc[4][2];
    #pragma unroll
    for (int i = 0; i < 4; i++) { acc[i][0] = 0ull; acc[i][1] = 0ull; }

    for (int p = 0; p < 4; p++) {
        __syncthreads();
        // stage A dup: As_dup[k][2b,2b+1] = xT[t0][p*64+k][b]  (straight f2 -> dup f4)
        {
            const float2* xsrc = (const float2*)(g_xT + ((long)t0 * ND + p * 64) * NB);
            float4* Ad4 = (float4*)As_dup;
            #pragma unroll
            for (int it = 0; it < 8; it++) {
                int f2 = it * 256 + tid;                 // 2048 f2 = 64k x 32
                float2 v = __ldg(&xsrc[f2]);
                Ad4[f2] = make_float4(v.x, v.x, v.y, v.y);
            }
        }
        // stage B: Bs[k][n] = wihT[p*64+k][n0+n]  (straight f4 copy)
        {
            const float4* wsrc = (const float4*)(g_wihT + (long)(p * 64) * NH + n0);
            #pragma unroll
            for (int it = 0; it < 4; it++) {
                int f4 = it * 256 + tid;                 // 1024 f4 = 64k x 16
                int k = f4 >> 4, n4 = f4 & 15;
                ((float4*)Bs)[f4] = __ldg(&wsrc[(long)k * (NH / 4) + n4]);
            }
        }
        __syncthreads();

        #pragma unroll 8
        for (int kk = 0; kk < 64; kk++) {
            const ulonglong2 bp  = *(const ulonglong2*)(Bs + kk * 64 + tx * 4);
            const ulonglong2 a01 = *(const ulonglong2*)(As_dup + kk * 128 + ty * 8);
            const ulonglong2 a23 = *(const ulonglong2*)(As_dup + kk * 128 + ty * 8 + 4);
            FMA2(acc[0][0], a01.x, bp.x); FMA2(acc[0][1], a01.x, bp.y);
            FMA2(acc[1][0], a01.y, bp.x); FMA2(acc[1][1], a01.y, bp.y);
            FMA2(acc[2][0], a23.x, bp.x); FMA2(acc[2][1], a23.x, bp.y);
            FMA2(acc[3][0], a23.y, bp.x); FMA2(acc[3][1], a23.y, bp.y);
        }
    }

    // store xprojT[t0][n0 + tx*4 + j][ty*4 .. +3]
    #pragma unroll
    for (int j = 0; j < 4; j++) {
        int jp = j >> 1;
        float4 v;
        if (j & 1) v = make_float4(hi32(acc[0][jp]), hi32(acc[1][jp]),
                                   hi32(acc[2][jp]), hi32(acc[3][jp]));
        else       v = make_float4(lo32(acc[0][jp]), hi32(acc[0][jp]) * 0.0f +
                                   lo32(acc[1][jp]), lo32(acc[2][jp]), lo32(acc[3][jp]));
        // (branch kept simple & explicit below instead)
        if (j & 1) {
            v = make_float4(hi32(acc[0][jp]), hi32(acc[1][jp]), hi32(acc[2][jp]), hi32(acc[3][jp]));
        } else {
            v = make_float4(lo32(acc[0][jp]), lo32(acc[1][jp]), lo32(acc[2][jp]), lo32(acc[3][jp]));
        }
        *(float4*)(g_xprojT + ((long)t0 * NH + n0 + tx * 4 + j) * NB + ty * 4) = v;
    }
}

// ---------------- kernel 2: persistent recurrence (R5, unchanged) ----------------
__global__ __launch_bounds__(256) void recur_kernel(
    const float* __restrict__ w_hh, const float* __restrict__ b_mod)
{
    extern __shared__ float sm[];
    float* As_dup = sm;                 // [128][128] floats, (h,h) duplicated pairs, 64 KB
    float* Bs = sm + 128 * 128;         // [128][64] floats (k-major), 32 KB

    const int tid = threadIdx.x;
    const int cta = blockIdx.x;
    const int nc = cta & 15;
    const int kc = cta >> 4;
    const int tx = tid & 15, ty = tid >> 4;

    // ---- one-time: W_hh slice transposed into persistent smem ----
    #pragma unroll
    for (int it = 0; it < 8; it++) {
        int f4 = it * 256 + tid;                 // 2048 float4 = 8192 floats
        int np = f4 >> 5, k0 = (f4 & 31) * 4;
        float4 w = __ldg((const float4*)(w_hh + (long)(nc * 64 + np) * NH + kc * 128 + k0));
        Bs[(k0 + 0) * 64 + np] = w.x;
        Bs[(k0 + 1) * 64 + np] = w.y;
        Bs[(k0 + 2) * 64 + np] = w.z;
        Bs[(k0 + 3) * 64 + np] = w.w;
    }
    __syncthreads();

    for (int t = 1; t < NT; t++) {
        // ---- wait: the two column groups covering chunk kc of z_{t-1} ----
        if (t > 1) {
            unsigned target = (unsigned)(8 * (t - 1));
            if (tid == 0)  while (ld_acq(&g_arr[2 * kc]) < target) {}
            if (tid == 32) while (ld_acq(&g_arr[2 * kc + 1]) < target) {}
        }
        __syncthreads();

        // ---- stage: h_{t-1} = modrelu(z_{t-1}) chunk kc, duplicated ----
        {
            const float2* zsrc = (const float2*)(g_xprojT +
                                 ((long)(t - 1) * NH + kc * 128) * NB);
            float4* Ad4 = (float4*)As_dup;
            #pragma unroll
            for (int it = 0; it < 16; it++) {
                int f2 = it * 256 + tid;
                int n = kc * 128 + (f2 >> 5);
                float2 z = __ldcg(&zsrc[f2]);
                float bm = __ldg(&b_mod[n]);
                float hx = modrelu(z.x, bm);
                float hy = modrelu(z.y, bm);
                Ad4[f2] = make_float4(hx, hx, hy, hy);
            }
        }
        __syncthreads();

        // ---- GEMM: 128 kk x (3 LDS.128 + 8 FFMA2) ----
        u64 acc[4][2];
        #pragma unroll
        for (int i = 0; i < 4; i++) { acc[i][0] = 0ull; acc[i][1] = 0ull; }

        #pragma unroll 8
        for (int kk = 0; kk < 128; kk++) {
            const ulonglong2 bp  = *(const ulonglong2*)(Bs + kk * 64 + tx * 4);
            const ulonglong2 a01 = *(const ulonglong2*)(As_dup + kk * 128 + ty * 8);
            const ulonglong2 a23 = *(const ulonglong2*)(As_dup + kk * 128 + ty * 8 + 4);
            FMA2(acc[0][0], a01.x, bp.x); FMA2(acc[0][1], a01.x, bp.y);
            FMA2(acc[1][0], a01.y, bp.x); FMA2(acc[1][1], a01.y, bp.y);
            FMA2(acc[2][0], a23.x, bp.x); FMA2(acc[2][1], a23.x, bp.y);
            FMA2(acc[3][0], a23.y, bp.x); FMA2(acc[3][1], a23.y, bp.y);
        }

        // ---- red-accumulate partials into z_t (vector atomics) ----
        {
            float* zdst = g_xprojT + ((long)t * NH + nc * 64) * NB;
            #pragma unroll
            for (int j = 0; j < 4; j++) {
                int jp = j >> 1;
                float v0, v1, v2, v3;
                if (j & 1) { v0 = hi32(acc[0][jp]); v1 = hi32(acc[1][jp]);
                             v2 = hi32(acc[2][jp]); v3 = hi32(acc[3][jp]); }
                else       { v0 = lo32(acc[0][jp]); v1 = lo32(acc[1][jp]);
                             v2 = lo32(acc[2][jp]); v3 = lo32(acc[3][jp]); }
                red_add_v4(zdst + (long)(tx * 4 + j) * NB + ty * 4, v0, v1, v2, v3);
            }
        }

        // ---- arrive ----
        __syncthreads();
        if (tid == 0) {
            __threadfence();
            atomicAdd(&g_arr[nc], 1u);
        }
    }
}

// ---------------- kernel 3: fc head (R5, unchanged) ----------------
__global__ __launch_bounds__(256) void fc_kernel(
    const float* __restrict__ w_fc, const float* __restrict__ b_fc,
    const float* __restrict__ b_mod, float* __restrict__ out)
{
    __shared__ float As[64][64];   // [k][b] = h_last slab
    __shared__ float Bs[64][64];   // [k][c']
    const int n0 = blockIdx.x * 64;
    const int tid = threadIdx.x;
    const int tx = tid & 15, ty = tid >> 4;
    const float* zlast = g_xprojT + (long)(NT - 1) * NH * NB;
    float acc[4][4] = {};

    for (int s = 0; s < 16; s++) {
        __syncthreads();
        #pragma unroll
        for (int it = 0; it < 4; it++) {
            int f4 = it * 256 + tid;
            int n = s * 64 + (f4 >> 4);
            float4 z = __ldcg((const float4*)zlast + s * 1024 + f4);
            float bm = __ldg(&b_mod[n]);
            float4 h;
            h.x = modrelu(z.x, bm); h.y = modrelu(z.y, bm);
            h.z = modrelu(z.z, bm); h.w = modrelu(z.w, bm);
            ((float4*)As)[f4] = h;
        }
        #pragma unroll
        for (int it = 0; it < 4; it++) {
            int f4 = it * 256 + tid;
            int np = f4 >> 4, k0 = (f4 & 15) * 4;
            int row = n0 + np; if (row >= NC) row = NC - 1;
            float4 w = *(const float4*)(w_fc + (long)row * NH + s * 64 + k0);
            Bs[k0 + 0][np] = w.x; Bs[k0 + 1][np] = w.y;
            Bs[k0 + 2][np] = w.z; Bs[k0 + 3][np] = w.w;
        }
        __syncthreads();
        #pragma unroll 8
        for (int kk = 0; kk < 64; kk++) {
            float4 av = *(const float4*)(&As[kk][ty * 4]);
            float4 bv = *(const float4*)(&Bs[kk][tx * 4]);
            float a[4] = {av.x, av.y, av.z, av.w};
            float b[4] = {bv.x, bv.y, bv.z, bv.w};
            #pragma unroll
            for (int i = 0; i < 4; i++)
                #pragma unroll
                for (int j = 0; j < 4; j++)
                    acc[i][j] += a[i] * b[j];
        }
    }
    #pragma unroll
    for (int i = 0; i < 4; i++) {
        #pragma unroll
        for (int j = 0; j < 4; j++) {
            int c = n0 + tx * 4 + j;
            if (c < NC) out[(long)(ty * 4 + i) * NC + c] = acc[i][j] + __ldg(&b_fc[c]);
        }
    }
}

// ---------------- launch ----------------
extern "C" void kernel_launch(void* const* d_in, const int* in_sizes, int n_in,
                              void* d_out, int out_size)
{
    const float* x     = (const float*)d_in[0];  // [64,1024,256]
    const float* w_ih  = (const float*)d_in[1];  // [1024,256]
    const float* w_hh  = (const float*)d_in[2];  // [1024,1024]
    const float* b_mod = (const float*)d_in[3];  // [1024]
    const float* w_fc  = (const float*)d_in[4];  // [1000,1024]
    const float* b_fc  = (const float*)d_in[5];  // [1000]
    float* out = (float*)d_out;                  // [64,1000]

    cudaFuncSetAttribute(recur_kernel, cudaFuncAttributeMaxDynamicSharedMemorySize, 98304);

    init_kernel<<<1, 32>>>();
    xpose_kernel<<<dim3(NT, ND / 64), 256>>>(x);
    wpose_kernel<<<dim3(NH / 64, ND / 64), 256>>>(w_ih);
    xproj_kernel<<<dim3(NT, NH / 64), 256>>>();
    recur_kernel<<<RCTAS, 256, 98304>>>(w_hh, b_mod);
    fc_kernel<<<(NC + 63) / 64, 256>>>(w_fc, b_fc, b_mod, out);
}